// round 4
// baseline (speedup 1.0000x reference)
#include <cuda_runtime.h>
#include <math.h>

#define MAXB   4
#define MAXN   16384
#define MAXG   32
#define MAXBLK 256
#define ABLK   128
#define MAXC   16

#ifndef M_PI
#define M_PI 3.14159265358979323846
#endif

// ---------------- device scratch (no allocations allowed) ----------------
__device__ int                  g_lab[MAXB * MAXN];
__device__ float                g_mg[MAXB * MAXN * 5];
__device__ unsigned long long   g_best[MAXB * MAXG];   // zero-init; reset each run
__device__ double               g_part[MAXB * MAXBLK * 3];
__device__ int                  g_cnt1[MAXB];          // assign done-counters
__device__ int                  g_cnt2;                // loss done-counter

// ---------------- helpers ----------------
__device__ __forceinline__ float jrem180(float x) {
    float r = fmodf(x, 180.0f);
    if (r < 0.0f) r += 180.0f;
    return r;
}

// Sutherland–Hodgman: clip convex CCW quad A by convex CCW quad B, shoelace area.
__device__ float quad_clip_area(const float* axp, const float* ayp,
                                const float* bxp, const float* byp)
{
    float Px[8], Py[8], Qx[8], Qy[8];
    int n = 4;
    #pragma unroll
    for (int k = 0; k < 4; k++) { Px[k] = axp[k]; Py[k] = ayp[k]; }

    #pragma unroll
    for (int j = 0; j < 4; j++) {
        float cx0 = bxp[j], cy0 = byp[j];
        int j1 = (j + 1) & 3;
        float ex = bxp[j1] - cx0, ey = byp[j1] - cy0;
        int m = 0;
        for (int k = 0; k < n; k++) {
            int k1 = (k + 1 == n) ? 0 : k + 1;
            float x0 = Px[k],  y0 = Py[k];
            float x1 = Px[k1], y1 = Py[k1];
            float d0 = ex * (y0 - cy0) - ey * (x0 - cx0);
            float d1 = ex * (y1 - cy0) - ey * (x1 - cx0);
            bool in0 = d0 >= 0.0f, in1 = d1 >= 0.0f;
            if (in0) { Qx[m] = x0; Qy[m] = y0; m++; }
            if (in0 != in1) {
                float t = d0 / (d0 - d1);
                Qx[m] = x0 + t * (x1 - x0);
                Qy[m] = y0 + t * (y1 - y0);
                m++;
            }
        }
        n = m;
        if (n == 0) break;
        for (int k = 0; k < n; k++) { Px[k] = Qx[k]; Py[k] = Qy[k]; }
    }

    if (n < 3) return 0.0f;
    float s = 0.0f;
    for (int k = 0; k < n; k++) {
        int k1 = (k + 1 == n) ? 0 : k + 1;
        s += Px[k] * Py[k1] - Px[k1] * Py[k];
    }
    return 0.5f * fabsf(s);
}

__device__ __forceinline__ void make_corners_f(float cx, float cy, float w,
                                               float h, float th,
                                               float* X, float* Y)
{
    float r = th * (float)(M_PI / 180.0);
    float c = cosf(r), s = sinf(r);
    float lx[4] = {-0.5f * w,  0.5f * w, 0.5f * w, -0.5f * w};
    float ly[4] = {-0.5f * h, -0.5f * h, 0.5f * h,  0.5f * h};
    #pragma unroll
    for (int k = 0; k < 4; k++) {
        X[k] = cx + lx[k] * c - ly[k] * s;
        Y[k] = cy + lx[k] * s + ly[k] * c;
    }
}

// ---------------- kernel 1: assign + (last block per image) force match ---
__global__ void assign_kernel(const float* __restrict__ anchors,
                              const float* __restrict__ gt_boxes,
                              const int*   __restrict__ gt_labels,
                              int N, int G)
{
    int b  = blockIdx.y;
    int i0 = blockIdx.x * ABLK;
    int t  = threadIdx.x;
    int i  = i0 + t;

    __shared__ float sgx[MAXG][4], sgy[MAXG][4];
    __shared__ float sgb[MAXG][5];
    __shared__ float sg_sz[MAXG];
    __shared__ float sg_area[MAXG];
    __shared__ int   s_gl[MAXG];
    __shared__ unsigned long long s_best[MAXG];
    __shared__ float s_anc[ABLK][5];
    __shared__ float s_acx[ABLK][4], s_acy[ABLK][4];
    __shared__ float s_iou[ABLK][MAXG];
    __shared__ int   s_q[ABLK * MAXG];
    __shared__ int   s_qn;
    __shared__ int   s_last;

    if (t == 0) { s_qn = 0; s_last = 0; }
    if (t < G) {
        const float* gb = gt_boxes + (size_t)(b * G + t) * 5;
        float w = gb[2], h = gb[3];
        #pragma unroll
        for (int k = 0; k < 5; k++) sgb[t][k] = gb[k];
        sg_sz[t]   = fmaxf(w, h);
        sg_area[t] = w * h;
        s_gl[t]    = gt_labels[b * G + t];
        make_corners_f(gb[0], gb[1], w, h, gb[4], sgx[t], sgy[t]);
        s_best[t] = 0ULL;
    }
    if (i < N) {
        const float* ab = anchors + (size_t)i * 5;
        #pragma unroll
        for (int k = 0; k < 5; k++) s_anc[t][k] = ab[k];
        make_corners_f(ab[0], ab[1], ab[2], ab[3], ab[4], s_acx[t], s_acy[t]);
    }
    for (int j = 0; j < G; j++) s_iou[t][j] = 0.0f;
    __syncthreads();

    // phase 1: gate, build pair queue
    if (i < N) {
        float ax = s_anc[t][0], ay = s_anc[t][1];
        float a_sz = fmaxf(s_anc[t][2], s_anc[t][3]);
        for (int j = 0; j < G; j++) {
            float dx = ax - sgb[j][0];
            float dy = ay - sgb[j][1];
            float gate = (a_sz + sg_sz[j]) * 0.7f;
            if (sqrtf(dx * dx + dy * dy) < gate) {
                int p = atomicAdd(&s_qn, 1);
                s_q[p] = (t << 5) | j;
            }
        }
    }
    __syncthreads();

    // phase 2: all threads drain the queue (load-balanced)
    int qn = s_qn;
    for (int q = t; q < qn; q += ABLK) {
        int e  = s_q[q];
        int li = e >> 5;
        int j  = e & 31;
        float a_area = s_anc[li][2] * s_anc[li][3];
        float inter = quad_clip_area(s_acx[li], s_acy[li], sgx[j], sgy[j]);
        s_iou[li][j] = inter / (a_area + sg_area[j] - inter + 1e-8f);
    }
    __syncthreads();

    // phase 3: per-anchor argmax, thresholds, per-GT best via packed atomicMax
    if (i < N) {
        float best_iou = 0.0f;
        int   best_j   = 0;
        for (int j = 0; j < G; j++) {
            float iou = s_iou[t][j];
            if (iou > best_iou) { best_iou = iou; best_j = j; }
            if (iou > 0.0f) {
                unsigned long long key =
                    ((unsigned long long)__float_as_uint(iou) << 32)
                    | (unsigned long long)(0xFFFFFFFFu - (unsigned)i);
                atomicMax(&s_best[j], key);
            }
        }
        int lab;
        if (best_iou >= 0.5f) {
            lab = s_gl[best_j] + 1;
            #pragma unroll
            for (int k = 0; k < 5; k++)
                g_mg[(size_t)(b * MAXN + i) * 5 + k] = sgb[best_j][k];
        } else {
            lab = (best_iou < 0.4f) ? 0 : -1;
        }
        g_lab[b * MAXN + i] = lab;
    }
    __syncthreads();

    if (t < G && s_best[t] != 0ULL)
        atomicMax(&g_best[b * MAXG + t], s_best[t]);

    // last-block-per-image: sequential force match (reference's G-loop order)
    __syncthreads();
    if (t == 0) {
        __threadfence();
        int v = atomicAdd(&g_cnt1[b], 1);
        if (v == (int)gridDim.x - 1) s_last = 1;
    }
    __syncthreads();
    if (s_last && t == 0) {
        __threadfence();  // acquire: see all blocks' g_lab/g_mg/g_best
        for (int j = 0; j < G; j++) {
            unsigned long long key = g_best[b * MAXG + j];
            g_best[b * MAXG + j] = 0ULL;
            if ((key >> 32) != 0ULL) {
                int bi = (int)(0xFFFFFFFFu - (unsigned)(key & 0xFFFFFFFFu));
                int gl = s_gl[j] + 1;
                if (g_lab[b * MAXN + bi] != gl) {
                    g_lab[b * MAXN + bi] = gl;
                    #pragma unroll
                    for (int k = 0; k < 5; k++)
                        g_mg[(size_t)(b * MAXN + bi) * 5 + k] = sgb[j][k];
                }
            }
        }
        g_cnt1[b] = 0;  // reset for next graph replay
    }
}

// ---------------- kernel 2: loss + (last block) final reduction -----------
__global__ void loss_kernel(const float* __restrict__ logits,
                            const float* __restrict__ box_reg,
                            const float* __restrict__ anchors,
                            float* __restrict__ out,
                            int N, int C, int B)
{
    int b  = blockIdx.y;
    int i0 = blockIdx.x * ABLK;
    int t  = threadIdx.x;
    int i  = i0 + t;

    __shared__ float  slog[ABLK * MAXC];
    __shared__ double sf[ABLK], sr[ABLK], sn[ABLK];
    __shared__ int    s_last;

    if (t == 0) s_last = 0;

    // coalesced stage of this block's logits into smem
    {
        int cnt = min(ABLK, N - i0);
        const float* base = logits + ((size_t)b * N + i0) * (size_t)C;
        int tot = cnt * C;
        for (int k = t; k < tot; k += ABLK) slog[k] = base[k];
    }
    __syncthreads();

    double fl_sum = 0.0, reg_sum = 0.0, np = 0.0;

    if (i < N) {
        int lab = g_lab[b * MAXN + i];
        bool valid = lab >= 0;
        bool pos   = lab > 0;

        if (valid) {
            const float* lp = &slog[t * C];
            int tc = lab - 1;
            float fl = 0.0f;
            for (int c = 0; c < C; c++) {
                float x = lp[c];
                bool tt = pos && (c == tc);
                float e     = __expf(-x);
                float denom = 1.0f + e;
                float L     = __logf(denom);
                float inv   = __fdividef(1.0f, denom);  // sigmoid(x)
                float om    = tt ? e * inv : inv;       // 1 - p_t
                float alpha = tt ? 0.25f : 0.75f;
                float bce   = tt ? L : (L + x);
                fl += alpha * om * om * bce;
            }
            fl_sum = (double)fl;
        }

        if (pos) {
            np = 1.0;
            const float* ab = anchors + (size_t)i * 5;
            const float* mg = &g_mg[(size_t)(b * MAXN + i) * 5];
            const float* br = box_reg + ((size_t)b * N + i) * 5;

            float dlt[5];
            dlt[0] = (mg[0] - ab[0]) / ab[2];
            dlt[1] = (mg[1] - ab[1]) / ab[3];
            dlt[2] = logf(mg[2] / ab[2]);
            dlt[3] = logf(mg[3] / ab[3]);
            dlt[4] = jrem180(mg[4] - ab[4] + 90.0f) - 90.0f;

            float l = 0.0f;
            #pragma unroll
            for (int k = 0; k < 4; k++) {
                float d = fabsf(br[k] - dlt[k]);
                l += (d < 1.0f) ? 0.5f * d * d : d - 0.5f;
            }
            float da = fabsf(jrem180(br[4] - dlt[4] + 90.0f) - 90.0f);
            l += (da < 1.0f) ? 0.5f * da * da : da - 0.5f;
            reg_sum = (double)l;
        }
    }

    sf[t] = fl_sum; sr[t] = reg_sum; sn[t] = np;
    __syncthreads();
    for (int s = ABLK / 2; s > 0; s >>= 1) {
        if (t < s) { sf[t] += sf[t + s]; sr[t] += sr[t + s]; sn[t] += sn[t + s]; }
        __syncthreads();
    }
    if (t == 0) {
        size_t o = (size_t)(b * MAXBLK + blockIdx.x) * 3;
        g_part[o + 0] = sf[0];
        g_part[o + 1] = sr[0];
        g_part[o + 2] = sn[0];
        __threadfence();
        int total = (int)(gridDim.x * gridDim.y);
        int v = atomicAdd(&g_cnt2, 1);
        if (v == total - 1) s_last = 1;
    }
    __syncthreads();

    if (s_last) {
        if (t == 0) __threadfence();  // acquire all g_part
        __syncthreads();
        int nblk = (int)gridDim.x;
        double cls_m = 0.0, reg_m = 0.0;
        for (int bb = 0; bb < B; bb++) {
            double f = 0.0, r = 0.0, n = 0.0;
            for (int k = t; k < nblk; k += ABLK) {
                size_t o = (size_t)(bb * MAXBLK + k) * 3;
                f += g_part[o + 0];
                r += g_part[o + 1];
                n += g_part[o + 2];
            }
            sf[t] = f; sr[t] = r; sn[t] = n;
            __syncthreads();
            for (int s = ABLK / 2; s > 0; s >>= 1) {
                if (t < s) { sf[t] += sf[t+s]; sr[t] += sr[t+s]; sn[t] += sn[t+s]; }
                __syncthreads();
            }
            if (t == 0) {
                double npos = (sn[0] < 1.0) ? 1.0 : sn[0];
                cls_m += sf[0] / npos;
                reg_m += sr[0] / npos;
            }
            __syncthreads();
        }
        if (t == 0) {
            cls_m /= (double)B;
            reg_m /= (double)B;
            out[0] = (float)(cls_m + reg_m);
            out[1] = (float)cls_m;
            out[2] = (float)reg_m;
            g_cnt2 = 0;  // reset for next graph replay
        }
    }
}

// ---------------- launch ----------------
extern "C" void kernel_launch(void* const* d_in, const int* in_sizes, int n_in,
                              void* d_out, int out_size)
{
    const float* logits  = (const float*)d_in[0];
    const float* breg    = (const float*)d_in[1];
    const float* anchors = (const float*)d_in[2];
    const float* gtb     = (const float*)d_in[3];
    const int*   gtl     = (const int*)d_in[4];

    int N = in_sizes[2] / 5;              // anchors: (N,5)
    int B = in_sizes[1] / (5 * N);        // box_reg: (B,N,5)
    int C = in_sizes[0] / (B * N);        // logits : (B,N,C)
    int G = in_sizes[4] / B;              // labels : (B,G)

    dim3 ag((N + ABLK - 1) / ABLK, B);
    assign_kernel<<<ag, ABLK>>>(anchors, gtb, gtl, N, G);

    dim3 lg((N + ABLK - 1) / ABLK, B);
    loss_kernel<<<lg, ABLK>>>(logits, breg, anchors, (float*)d_out, N, C, B);
}

// round 5
// speedup vs baseline: 1.0159x; 1.0159x over previous
#include <cuda_runtime.h>
#include <math.h>

#define MAXB   4
#define MAXN   16384
#define MAXG   32
#define MAXPB  1024      // max partial blocks per image (N/APB)
#define ABLK   128
#define APB    16        // anchors per loss block
#define LBLK   256       // loss block threads

#ifndef M_PI
#define M_PI 3.14159265358979323846
#endif

// ---------------- device scratch (no allocations allowed) ----------------
__device__ int                  g_lab[MAXB * MAXN];
__device__ float                g_mg[MAXB * MAXN * 5];
__device__ unsigned long long   g_best[MAXB * MAXG];   // zero-init; reset each run
__device__ double               g_part[MAXB * MAXPB * 3];
__device__ int                  g_cnt1[MAXB];          // assign done-counters
__device__ int                  g_cnt2;                // loss done-counter

// ---------------- helpers ----------------
__device__ __forceinline__ float jrem180(float x) {
    float r = fmodf(x, 180.0f);
    if (r < 0.0f) r += 180.0f;
    return r;
}

// Sutherland–Hodgman: clip convex CCW quad A by convex CCW quad B, shoelace area.
__device__ float quad_clip_area(const float* axp, const float* ayp,
                                const float* bxp, const float* byp)
{
    float Px[8], Py[8], Qx[8], Qy[8];
    int n = 4;
    #pragma unroll
    for (int k = 0; k < 4; k++) { Px[k] = axp[k]; Py[k] = ayp[k]; }

    #pragma unroll
    for (int j = 0; j < 4; j++) {
        float cx0 = bxp[j], cy0 = byp[j];
        int j1 = (j + 1) & 3;
        float ex = bxp[j1] - cx0, ey = byp[j1] - cy0;
        int m = 0;
        for (int k = 0; k < n; k++) {
            int k1 = (k + 1 == n) ? 0 : k + 1;
            float x0 = Px[k],  y0 = Py[k];
            float x1 = Px[k1], y1 = Py[k1];
            float d0 = ex * (y0 - cy0) - ey * (x0 - cx0);
            float d1 = ex * (y1 - cy0) - ey * (x1 - cx0);
            bool in0 = d0 >= 0.0f, in1 = d1 >= 0.0f;
            if (in0) { Qx[m] = x0; Qy[m] = y0; m++; }
            if (in0 != in1) {
                float t = d0 / (d0 - d1);
                Qx[m] = x0 + t * (x1 - x0);
                Qy[m] = y0 + t * (y1 - y0);
                m++;
            }
        }
        n = m;
        if (n == 0) break;
        for (int k = 0; k < n; k++) { Px[k] = Qx[k]; Py[k] = Qy[k]; }
    }

    if (n < 3) return 0.0f;
    float s = 0.0f;
    for (int k = 0; k < n; k++) {
        int k1 = (k + 1 == n) ? 0 : k + 1;
        s += Px[k] * Py[k1] - Px[k1] * Py[k];
    }
    return 0.5f * fabsf(s);
}

__device__ __forceinline__ void make_corners_f(float cx, float cy, float w,
                                               float h, float th,
                                               float* X, float* Y)
{
    float r = th * (float)(M_PI / 180.0);
    float c = cosf(r), s = sinf(r);
    float lx[4] = {-0.5f * w,  0.5f * w, 0.5f * w, -0.5f * w};
    float ly[4] = {-0.5f * h, -0.5f * h, 0.5f * h,  0.5f * h};
    #pragma unroll
    for (int k = 0; k < 4; k++) {
        X[k] = cx + lx[k] * c - ly[k] * s;
        Y[k] = cy + lx[k] * s + ly[k] * c;
    }
}

// ---------------- kernel 1: assign + (last block per image) force match ---
__global__ void assign_kernel(const float* __restrict__ anchors,
                              const float* __restrict__ gt_boxes,
                              const int*   __restrict__ gt_labels,
                              int N, int G)
{
    int b  = blockIdx.y;
    int i0 = blockIdx.x * ABLK;
    int t  = threadIdx.x;
    int i  = i0 + t;

    __shared__ float sgx[MAXG][4], sgy[MAXG][4];
    __shared__ float sgb[MAXG][5];
    __shared__ float sg_sz[MAXG];
    __shared__ float sg_area[MAXG];
    __shared__ int   s_gl[MAXG];
    __shared__ unsigned long long s_best[MAXG];
    __shared__ float s_anc[ABLK][5];
    __shared__ float s_acx[ABLK][4], s_acy[ABLK][4];
    __shared__ float s_iou[ABLK][MAXG];
    __shared__ int   s_q[ABLK * MAXG];
    __shared__ int   s_qn;
    __shared__ int   s_last;

    if (t == 0) { s_qn = 0; s_last = 0; }
    if (t < G) {
        const float* gb = gt_boxes + (size_t)(b * G + t) * 5;
        float w = gb[2], h = gb[3];
        #pragma unroll
        for (int k = 0; k < 5; k++) sgb[t][k] = gb[k];
        sg_sz[t]   = fmaxf(w, h);
        sg_area[t] = w * h;
        s_gl[t]    = gt_labels[b * G + t];
        make_corners_f(gb[0], gb[1], w, h, gb[4], sgx[t], sgy[t]);
        s_best[t] = 0ULL;
    }
    if (i < N) {
        const float* ab = anchors + (size_t)i * 5;
        #pragma unroll
        for (int k = 0; k < 5; k++) s_anc[t][k] = ab[k];
        make_corners_f(ab[0], ab[1], ab[2], ab[3], ab[4], s_acx[t], s_acy[t]);
    }
    for (int j = 0; j < G; j++) s_iou[t][j] = 0.0f;
    __syncthreads();

    // phase 1: gate, build pair queue
    if (i < N) {
        float ax = s_anc[t][0], ay = s_anc[t][1];
        float a_sz = fmaxf(s_anc[t][2], s_anc[t][3]);
        for (int j = 0; j < G; j++) {
            float dx = ax - sgb[j][0];
            float dy = ay - sgb[j][1];
            float gate = (a_sz + sg_sz[j]) * 0.7f;
            if (sqrtf(dx * dx + dy * dy) < gate) {
                int p = atomicAdd(&s_qn, 1);
                s_q[p] = (t << 5) | j;
            }
        }
    }
    __syncthreads();

    // phase 2: all threads drain the queue (load-balanced)
    int qn = s_qn;
    for (int q = t; q < qn; q += ABLK) {
        int e  = s_q[q];
        int li = e >> 5;
        int j  = e & 31;
        float a_area = s_anc[li][2] * s_anc[li][3];
        float inter = quad_clip_area(s_acx[li], s_acy[li], sgx[j], sgy[j]);
        s_iou[li][j] = inter / (a_area + sg_area[j] - inter + 1e-8f);
    }
    __syncthreads();

    // phase 3: per-anchor argmax, thresholds, per-GT best via packed atomicMax
    if (i < N) {
        float best_iou = 0.0f;
        int   best_j   = 0;
        for (int j = 0; j < G; j++) {
            float iou = s_iou[t][j];
            if (iou > best_iou) { best_iou = iou; best_j = j; }
            if (iou > 0.0f) {
                unsigned long long key =
                    ((unsigned long long)__float_as_uint(iou) << 32)
                    | (unsigned long long)(0xFFFFFFFFu - (unsigned)i);
                atomicMax(&s_best[j], key);
            }
        }
        int lab;
        if (best_iou >= 0.5f) {
            lab = s_gl[best_j] + 1;
            #pragma unroll
            for (int k = 0; k < 5; k++)
                g_mg[(size_t)(b * MAXN + i) * 5 + k] = sgb[best_j][k];
        } else {
            lab = (best_iou < 0.4f) ? 0 : -1;
        }
        g_lab[b * MAXN + i] = lab;
    }
    __syncthreads();

    if (t < G && s_best[t] != 0ULL)
        atomicMax(&g_best[b * MAXG + t], s_best[t]);

    // last-block-per-image: sequential force match (reference's G-loop order)
    __syncthreads();
    if (t == 0) {
        __threadfence();
        int v = atomicAdd(&g_cnt1[b], 1);
        if (v == (int)gridDim.x - 1) s_last = 1;
    }
    __syncthreads();
    if (s_last && t == 0) {
        __threadfence();  // acquire: see all blocks' g_lab/g_mg/g_best
        for (int j = 0; j < G; j++) {
            unsigned long long key = g_best[b * MAXG + j];
            g_best[b * MAXG + j] = 0ULL;
            if ((key >> 32) != 0ULL) {
                int bi = (int)(0xFFFFFFFFu - (unsigned)(key & 0xFFFFFFFFu));
                int gl = s_gl[j] + 1;
                if (g_lab[b * MAXN + bi] != gl) {
                    g_lab[b * MAXN + bi] = gl;
                    #pragma unroll
                    for (int k = 0; k < 5; k++)
                        g_mg[(size_t)(b * MAXN + bi) * 5 + k] = sgb[j][k];
                }
            }
        }
        g_cnt1[b] = 0;  // reset for next graph replay
    }
}

// ---------------- kernel 2: loss, thread per (anchor, class) --------------
// block = 256 threads = 16 anchors x 16 class lanes (C=15 padded to 16)
__global__ void loss_kernel(const float* __restrict__ logits,
                            const float* __restrict__ box_reg,
                            const float* __restrict__ anchors,
                            float* __restrict__ out,
                            int N, int C, int B)
{
    int b = blockIdx.y;
    int t = threadIdx.x;
    int a = t >> 4;          // anchor slot in block
    int c = t & 15;          // class lane
    int i = blockIdx.x * APB + a;

    __shared__ float s_f[APB], s_r[APB], s_n[APB];
    __shared__ int   s_last;
    if (t == 0) s_last = 0;

    float fl = 0.0f, rl = 0.0f, np = 0.0f;
    int lab = -1;

    if (i < N) {
        lab = g_lab[b * MAXN + i];
        bool pos = lab > 0;
        if (lab >= 0 && c < C) {
            float x = logits[((size_t)b * N + i) * (size_t)C + c];
            bool tt = pos && (c == lab - 1);
            float e     = __expf(-x);
            float denom = 1.0f + e;
            float L     = __logf(denom);
            float inv   = __fdividef(1.0f, denom);  // sigmoid(x)
            float om    = tt ? e * inv : inv;       // 1 - p_t
            float alpha = tt ? 0.25f : 0.75f;
            float bce   = tt ? L : (L + x);
            fl = alpha * om * om * bce;
        }
    }

    // 16-lane segmented reduce of focal terms
    #pragma unroll
    for (int off = 8; off > 0; off >>= 1)
        fl += __shfl_down_sync(0xFFFFFFFFu, fl, off, 16);

    // lane 0 of each group: reg loss for positive anchors
    if (c == 0 && i < N && lab > 0) {
        np = 1.0f;
        const float* ab = anchors + (size_t)i * 5;
        const float* mg = &g_mg[(size_t)(b * MAXN + i) * 5];
        const float* br = box_reg + ((size_t)b * N + i) * 5;

        float dlt[5];
        dlt[0] = (mg[0] - ab[0]) / ab[2];
        dlt[1] = (mg[1] - ab[1]) / ab[3];
        dlt[2] = logf(mg[2] / ab[2]);
        dlt[3] = logf(mg[3] / ab[3]);
        dlt[4] = jrem180(mg[4] - ab[4] + 90.0f) - 90.0f;

        float l = 0.0f;
        #pragma unroll
        for (int k = 0; k < 4; k++) {
            float d = fabsf(br[k] - dlt[k]);
            l += (d < 1.0f) ? 0.5f * d * d : d - 0.5f;
        }
        float da = fabsf(jrem180(br[4] - dlt[4] + 90.0f) - 90.0f);
        l += (da < 1.0f) ? 0.5f * da * da : da - 0.5f;
        rl = l;
    }

    if (c == 0) { s_f[a] = fl; s_r[a] = rl; s_n[a] = np; }
    __syncthreads();

    // warp 0, lanes 0..15: reduce the 16 group sums, write block partial
    if (t < APB) {
        float f = s_f[t], r = s_r[t], n = s_n[t];
        #pragma unroll
        for (int off = 8; off > 0; off >>= 1) {
            f += __shfl_down_sync(0x0000FFFFu, f, off, 16);
            r += __shfl_down_sync(0x0000FFFFu, r, off, 16);
            n += __shfl_down_sync(0x0000FFFFu, n, off, 16);
        }
        if (t == 0) {
            size_t o = (size_t)(b * MAXPB + blockIdx.x) * 3;
            g_part[o + 0] = (double)f;
            g_part[o + 1] = (double)r;
            g_part[o + 2] = (double)n;
            __threadfence();
            int total = (int)(gridDim.x * gridDim.y);
            int v = atomicAdd(&g_cnt2, 1);
            if (v == total - 1) s_last = 1;
        }
    }
    __syncthreads();

    // last block overall: final reduction of all partials
    if (s_last) {
        if (t == 0) __threadfence();  // acquire all g_part
        __syncthreads();
        __shared__ double df[LBLK], dr[LBLK], dn[LBLK];
        int nblk = (int)gridDim.x;
        double cls_m = 0.0, reg_m = 0.0;
        for (int bb = 0; bb < B; bb++) {
            double f = 0.0, r = 0.0, n = 0.0;
            for (int k = t; k < nblk; k += LBLK) {
                size_t o = (size_t)(bb * MAXPB + k) * 3;
                f += g_part[o + 0];
                r += g_part[o + 1];
                n += g_part[o + 2];
            }
            df[t] = f; dr[t] = r; dn[t] = n;
            __syncthreads();
            for (int s = LBLK / 2; s > 0; s >>= 1) {
                if (t < s) { df[t] += df[t+s]; dr[t] += dr[t+s]; dn[t] += dn[t+s]; }
                __syncthreads();
            }
            if (t == 0) {
                double npos = (dn[0] < 1.0) ? 1.0 : dn[0];
                cls_m += df[0] / npos;
                reg_m += dr[0] / npos;
            }
            __syncthreads();
        }
        if (t == 0) {
            cls_m /= (double)B;
            reg_m /= (double)B;
            out[0] = (float)(cls_m + reg_m);
            out[1] = (float)cls_m;
            out[2] = (float)reg_m;
            g_cnt2 = 0;  // reset for next graph replay
        }
    }
}

// ---------------- launch ----------------
extern "C" void kernel_launch(void* const* d_in, const int* in_sizes, int n_in,
                              void* d_out, int out_size)
{
    const float* logits  = (const float*)d_in[0];
    const float* breg    = (const float*)d_in[1];
    const float* anchors = (const float*)d_in[2];
    const float* gtb     = (const float*)d_in[3];
    const int*   gtl     = (const int*)d_in[4];

    int N = in_sizes[2] / 5;              // anchors: (N,5)
    int B = in_sizes[1] / (5 * N);        // box_reg: (B,N,5)
    int C = in_sizes[0] / (B * N);        // logits : (B,N,C)
    int G = in_sizes[4] / B;              // labels : (B,G)

    dim3 ag((N + ABLK - 1) / ABLK, B);
    assign_kernel<<<ag, ABLK>>>(anchors, gtb, gtl, N, G);

    dim3 lg((N + APB - 1) / APB, B);
    loss_kernel<<<lg, LBLK>>>(logits, breg, anchors, (float*)d_out, N, C, B);
}

// round 6
// speedup vs baseline: 1.0227x; 1.0067x over previous
#include <cuda_runtime.h>
#include <math.h>

#define MAXB   4
#define MAXN   16384
#define MAXG   32
#define MAXPB  1024
#define ABLK   128
#define APB    16        // anchor groups per loss block
#define LANCH  128       // anchors per loss block
#define LITER  (LANCH / APB)   // 8
#define LBLK   256

#ifndef M_PI
#define M_PI 3.14159265358979323846
#endif

// ---------------- device scratch (no allocations allowed) ----------------
__device__ int                  g_lab[MAXB * MAXN];
__device__ float                g_mg[MAXB * MAXN * 5];
__device__ unsigned long long   g_best[MAXB * MAXG];   // zero-init; reset each run
__device__ double               g_part[MAXB * MAXPB * 3];
__device__ int                  g_cnt1[MAXB];
__device__ int                  g_cnt2;

// ---------------- helpers ----------------
__device__ __forceinline__ float jrem180(float x) {
    float r = fmodf(x, 180.0f);
    if (r < 0.0f) r += 180.0f;
    return r;
}

// Sutherland–Hodgman: clip convex CCW quad A by convex CCW quad B, shoelace area.
__device__ float quad_clip_area(const float* axp, const float* ayp,
                                const float* bxp, const float* byp)
{
    float Px[8], Py[8], Qx[8], Qy[8];
    int n = 4;
    #pragma unroll
    for (int k = 0; k < 4; k++) { Px[k] = axp[k]; Py[k] = ayp[k]; }

    #pragma unroll
    for (int j = 0; j < 4; j++) {
        float cx0 = bxp[j], cy0 = byp[j];
        int j1 = (j + 1) & 3;
        float ex = bxp[j1] - cx0, ey = byp[j1] - cy0;
        int m = 0;
        for (int k = 0; k < n; k++) {
            int k1 = (k + 1 == n) ? 0 : k + 1;
            float x0 = Px[k],  y0 = Py[k];
            float x1 = Px[k1], y1 = Py[k1];
            float d0 = ex * (y0 - cy0) - ey * (x0 - cx0);
            float d1 = ex * (y1 - cy0) - ey * (x1 - cx0);
            bool in0 = d0 >= 0.0f, in1 = d1 >= 0.0f;
            if (in0) { Qx[m] = x0; Qy[m] = y0; m++; }
            if (in0 != in1) {
                float t = d0 / (d0 - d1);
                Qx[m] = x0 + t * (x1 - x0);
                Qy[m] = y0 + t * (y1 - y0);
                m++;
            }
        }
        n = m;
        if (n == 0) break;
        for (int k = 0; k < n; k++) { Px[k] = Qx[k]; Py[k] = Qy[k]; }
    }

    if (n < 3) return 0.0f;
    float s = 0.0f;
    for (int k = 0; k < n; k++) {
        int k1 = (k + 1 == n) ? 0 : k + 1;
        s += Px[k] * Py[k1] - Px[k1] * Py[k];
    }
    return 0.5f * fabsf(s);
}

__device__ __forceinline__ void make_corners_f(float cx, float cy, float w,
                                               float h, float th,
                                               float* X, float* Y)
{
    float r = th * (float)(M_PI / 180.0);
    float s, c;
    __sincosf(r, &s, &c);
    float lx[4] = {-0.5f * w,  0.5f * w, 0.5f * w, -0.5f * w};
    float ly[4] = {-0.5f * h, -0.5f * h, 0.5f * h,  0.5f * h};
    #pragma unroll
    for (int k = 0; k < 4; k++) {
        X[k] = cx + lx[k] * c - ly[k] * s;
        Y[k] = cy + lx[k] * s + ly[k] * c;
    }
}

// ---------------- kernel 1: assign + (last block per image) force match ---
__global__ void assign_kernel(const float* __restrict__ anchors,
                              const float* __restrict__ gt_boxes,
                              const int*   __restrict__ gt_labels,
                              int N, int G)
{
    int b  = blockIdx.y;
    int i0 = blockIdx.x * ABLK;
    int t  = threadIdx.x;
    int i  = i0 + t;

    __shared__ float sgx[MAXG][4], sgy[MAXG][4];
    __shared__ float sgb[MAXG][5];
    __shared__ float sg_sz[MAXG];
    __shared__ float sg_area[MAXG];
    __shared__ int   s_gl[MAXG];
    __shared__ unsigned long long s_best[MAXG];
    __shared__ float s_anc[ABLK][5];
    __shared__ float s_acx[ABLK][4], s_acy[ABLK][4];
    __shared__ float s_iou[ABLK][MAXG];
    __shared__ int   s_q[ABLK * MAXG];
    __shared__ int   s_qn;
    __shared__ int   s_last;

    if (t == 0) { s_qn = 0; s_last = 0; }
    if (t < G) {
        const float* gb = gt_boxes + (size_t)(b * G + t) * 5;
        float w = gb[2], h = gb[3];
        #pragma unroll
        for (int k = 0; k < 5; k++) sgb[t][k] = gb[k];
        sg_sz[t]   = fmaxf(w, h);
        sg_area[t] = w * h;
        s_gl[t]    = gt_labels[b * G + t];
        make_corners_f(gb[0], gb[1], w, h, gb[4], sgx[t], sgy[t]);
        s_best[t] = 0ULL;
    }
    if (i < N) {
        const float* ab = anchors + (size_t)i * 5;
        #pragma unroll
        for (int k = 0; k < 5; k++) s_anc[t][k] = ab[k];
        make_corners_f(ab[0], ab[1], ab[2], ab[3], ab[4], s_acx[t], s_acy[t]);
    }
    for (int j = 0; j < G; j++) s_iou[t][j] = 0.0f;
    __syncthreads();

    // phase 1: gate, build pair queue
    if (i < N) {
        float ax = s_anc[t][0], ay = s_anc[t][1];
        float a_sz = fmaxf(s_anc[t][2], s_anc[t][3]);
        for (int j = 0; j < G; j++) {
            float dx = ax - sgb[j][0];
            float dy = ay - sgb[j][1];
            float gate = (a_sz + sg_sz[j]) * 0.7f;
            if (sqrtf(dx * dx + dy * dy) < gate) {
                int p = atomicAdd(&s_qn, 1);
                s_q[p] = (t << 5) | j;
            }
        }
    }
    __syncthreads();

    // phase 2: all threads drain the queue (load-balanced)
    int qn = s_qn;
    for (int q = t; q < qn; q += ABLK) {
        int e  = s_q[q];
        int li = e >> 5;
        int j  = e & 31;
        float a_area = s_anc[li][2] * s_anc[li][3];
        float inter = quad_clip_area(s_acx[li], s_acy[li], sgx[j], sgy[j]);
        s_iou[li][j] = inter / (a_area + sg_area[j] - inter + 1e-8f);
    }
    __syncthreads();

    // phase 3: per-anchor argmax, thresholds, per-GT best via packed atomicMax
    if (i < N) {
        float best_iou = 0.0f;
        int   best_j   = 0;
        for (int j = 0; j < G; j++) {
            float iou = s_iou[t][j];
            if (iou > best_iou) { best_iou = iou; best_j = j; }
            if (iou > 0.0f) {
                unsigned long long key =
                    ((unsigned long long)__float_as_uint(iou) << 32)
                    | (unsigned long long)(0xFFFFFFFFu - (unsigned)i);
                atomicMax(&s_best[j], key);
            }
        }
        int lab;
        if (best_iou >= 0.5f) {
            lab = s_gl[best_j] + 1;
            #pragma unroll
            for (int k = 0; k < 5; k++)
                g_mg[(size_t)(b * MAXN + i) * 5 + k] = sgb[best_j][k];
        } else {
            lab = (best_iou < 0.4f) ? 0 : -1;
        }
        g_lab[b * MAXN + i] = lab;
    }
    __syncthreads();

    if (t < G && s_best[t] != 0ULL)
        atomicMax(&g_best[b * MAXG + t], s_best[t]);

    __syncthreads();
    if (t == 0) {
        __threadfence();
        int v = atomicAdd(&g_cnt1[b], 1);
        if (v == (int)gridDim.x - 1) s_last = 1;
    }
    __syncthreads();
    if (s_last && t == 0) {
        __threadfence();
        for (int j = 0; j < G; j++) {
            unsigned long long key = g_best[b * MAXG + j];
            g_best[b * MAXG + j] = 0ULL;
            if ((key >> 32) != 0ULL) {
                int bi = (int)(0xFFFFFFFFu - (unsigned)(key & 0xFFFFFFFFu));
                int gl = s_gl[j] + 1;
                if (g_lab[b * MAXN + bi] != gl) {
                    g_lab[b * MAXN + bi] = gl;
                    #pragma unroll
                    for (int k = 0; k < 5; k++)
                        g_mg[(size_t)(b * MAXN + bi) * 5 + k] = sgb[j][k];
                }
            }
        }
        g_cnt1[b] = 0;
    }
}

// ---------------- kernel 2: loss, (anchor,class) threads, 8 anchors/thread
__global__ void loss_kernel(const float* __restrict__ logits,
                            const float* __restrict__ box_reg,
                            const float* __restrict__ anchors,
                            float* __restrict__ out,
                            int N, int C, int B)
{
    int b = blockIdx.y;
    int t = threadIdx.x;
    int a = t >> 4;          // group 0..15
    int c = t & 15;          // class lane
    int base = blockIdx.x * LANCH;

    __shared__ float s_f[APB], s_r[APB], s_n[APB];
    __shared__ int   s_last;
    if (t == 0) s_last = 0;

    float fl_acc = 0.0f, rl_acc = 0.0f, np_acc = 0.0f;

    #pragma unroll
    for (int it = 0; it < LITER; it++) {
        int i = base + it * APB + a;
        if (i >= N) break;
        int lab = g_lab[b * MAXN + i];
        bool pos = lab > 0;
        if (lab >= 0 && c < C) {
            float x = logits[((size_t)b * N + i) * (size_t)C + c];
            bool tt = pos && (c == lab - 1);
            float e     = __expf(-x);
            float denom = 1.0f + e;
            float L     = __logf(denom);
            float inv   = __fdividef(1.0f, denom);  // sigmoid(x)
            float om    = tt ? e * inv : inv;       // 1 - p_t
            float alpha = tt ? 0.25f : 0.75f;
            float bce   = tt ? L : (L + x);
            fl_acc += alpha * om * om * bce;
        }
        if (c == 0 && pos) {
            np_acc += 1.0f;
            const float* ab = anchors + (size_t)i * 5;
            const float* mg = &g_mg[(size_t)(b * MAXN + i) * 5];
            const float* br = box_reg + ((size_t)b * N + i) * 5;
            float dlt[5];
            dlt[0] = (mg[0] - ab[0]) / ab[2];
            dlt[1] = (mg[1] - ab[1]) / ab[3];
            dlt[2] = logf(mg[2] / ab[2]);
            dlt[3] = logf(mg[3] / ab[3]);
            dlt[4] = jrem180(mg[4] - ab[4] + 90.0f) - 90.0f;
            float l = 0.0f;
            #pragma unroll
            for (int k = 0; k < 4; k++) {
                float d = fabsf(br[k] - dlt[k]);
                l += (d < 1.0f) ? 0.5f * d * d : d - 0.5f;
            }
            float da = fabsf(jrem180(br[4] - dlt[4] + 90.0f) - 90.0f);
            l += (da < 1.0f) ? 0.5f * da * da : da - 0.5f;
            rl_acc += l;
        }
    }

    // 16-lane segmented reduce of focal sums
    #pragma unroll
    for (int off = 8; off > 0; off >>= 1)
        fl_acc += __shfl_down_sync(0xFFFFFFFFu, fl_acc, off, 16);

    if (c == 0) { s_f[a] = fl_acc; s_r[a] = rl_acc; s_n[a] = np_acc; }
    __syncthreads();

    if (t < APB) {
        float f = s_f[t], r = s_r[t], n = s_n[t];
        #pragma unroll
        for (int off = 8; off > 0; off >>= 1) {
            f += __shfl_down_sync(0x0000FFFFu, f, off, 16);
            r += __shfl_down_sync(0x0000FFFFu, r, off, 16);
            n += __shfl_down_sync(0x0000FFFFu, n, off, 16);
        }
        if (t == 0) {
            size_t o = (size_t)(b * MAXPB + blockIdx.x) * 3;
            g_part[o + 0] = (double)f;
            g_part[o + 1] = (double)r;
            g_part[o + 2] = (double)n;
            __threadfence();
            int total = (int)(gridDim.x * gridDim.y);
            int v = atomicAdd(&g_cnt2, 1);
            if (v == total - 1) s_last = 1;
        }
    }
    __syncthreads();

    if (s_last) {
        if (t == 0) __threadfence();
        __syncthreads();
        __shared__ double df[LBLK], dr[LBLK], dn[LBLK];
        int nblk = (int)gridDim.x;
        double cls_m = 0.0, reg_m = 0.0;
        for (int bb = 0; bb < B; bb++) {
            double f = 0.0, r = 0.0, n = 0.0;
            for (int k = t; k < nblk; k += LBLK) {
                size_t o = (size_t)(bb * MAXPB + k) * 3;
                f += g_part[o + 0];
                r += g_part[o + 1];
                n += g_part[o + 2];
            }
            df[t] = f; dr[t] = r; dn[t] = n;
            __syncthreads();
            for (int s = LBLK / 2; s > 0; s >>= 1) {
                if (t < s) { df[t] += df[t+s]; dr[t] += dr[t+s]; dn[t] += dn[t+s]; }
                __syncthreads();
            }
            if (t == 0) {
                double npos = (dn[0] < 1.0) ? 1.0 : dn[0];
                cls_m += df[0] / npos;
                reg_m += dr[0] / npos;
            }
            __syncthreads();
        }
        if (t == 0) {
            cls_m /= (double)B;
            reg_m /= (double)B;
            out[0] = (float)(cls_m + reg_m);
            out[1] = (float)cls_m;
            out[2] = (float)reg_m;
            g_cnt2 = 0;
        }
    }
}

// ---------------- launch ----------------
extern "C" void kernel_launch(void* const* d_in, const int* in_sizes, int n_in,
                              void* d_out, int out_size)
{
    const float* logits  = (const float*)d_in[0];
    const float* breg    = (const float*)d_in[1];
    const float* anchors = (const float*)d_in[2];
    const float* gtb     = (const float*)d_in[3];
    const int*   gtl     = (const int*)d_in[4];

    int N = in_sizes[2] / 5;
    int B = in_sizes[1] / (5 * N);
    int C = in_sizes[0] / (B * N);
    int G = in_sizes[4] / B;

    dim3 ag((N + ABLK - 1) / ABLK, B);
    assign_kernel<<<ag, ABLK>>>(anchors, gtb, gtl, N, G);

    dim3 lg((N + LANCH - 1) / LANCH, B);
    loss_kernel<<<lg, LBLK>>>(logits, breg, anchors, (float*)d_out, N, C, B);
}

// round 7
// speedup vs baseline: 1.0684x; 1.0447x over previous
#include <cuda_runtime.h>
#include <math.h>

#define MAXB   4
#define MAXN   16384
#define MAXG   32
#define MAXPB  1024
#define ABLK   64
#define LBLK   256
#define LGX    128       // loss grid.x per image

#ifndef M_PI
#define M_PI 3.14159265358979323846
#endif

// ---------------- device scratch (no allocations allowed) ----------------
__device__ int                  g_lab[MAXB * MAXN];
__device__ float                g_mg[MAXB * MAXN * 5];
__device__ unsigned long long   g_best[MAXB * MAXG];   // zero-init; reset each run
__device__ double               g_part[MAXB * MAXPB * 3];
__device__ int                  g_cnt1[MAXB];
__device__ int                  g_cnt2;

// ---------------- helpers ----------------
__device__ __forceinline__ float jrem180(float x) {
    float r = fmodf(x, 180.0f);
    if (r < 0.0f) r += 180.0f;
    return r;
}

// Sutherland–Hodgman: clip convex CCW quad A by convex CCW quad B, shoelace area.
__device__ float quad_clip_area(const float* axp, const float* ayp,
                                const float* bxp, const float* byp)
{
    float Px[8], Py[8], Qx[8], Qy[8];
    int n = 4;
    #pragma unroll
    for (int k = 0; k < 4; k++) { Px[k] = axp[k]; Py[k] = ayp[k]; }

    #pragma unroll
    for (int j = 0; j < 4; j++) {
        float cx0 = bxp[j], cy0 = byp[j];
        int j1 = (j + 1) & 3;
        float ex = bxp[j1] - cx0, ey = byp[j1] - cy0;
        int m = 0;
        for (int k = 0; k < n; k++) {
            int k1 = (k + 1 == n) ? 0 : k + 1;
            float x0 = Px[k],  y0 = Py[k];
            float x1 = Px[k1], y1 = Py[k1];
            float d0 = ex * (y0 - cy0) - ey * (x0 - cx0);
            float d1 = ex * (y1 - cy0) - ey * (x1 - cx0);
            bool in0 = d0 >= 0.0f, in1 = d1 >= 0.0f;
            if (in0) { Qx[m] = x0; Qy[m] = y0; m++; }
            if (in0 != in1) {
                float t = d0 / (d0 - d1);
                Qx[m] = x0 + t * (x1 - x0);
                Qy[m] = y0 + t * (y1 - y0);
                m++;
            }
        }
        n = m;
        if (n == 0) break;
        for (int k = 0; k < n; k++) { Px[k] = Qx[k]; Py[k] = Qy[k]; }
    }

    if (n < 3) return 0.0f;
    float s = 0.0f;
    for (int k = 0; k < n; k++) {
        int k1 = (k + 1 == n) ? 0 : k + 1;
        s += Px[k] * Py[k1] - Px[k1] * Py[k];
    }
    return 0.5f * fabsf(s);
}

__device__ __forceinline__ void make_corners_f(float cx, float cy, float w,
                                               float h, float th,
                                               float* X, float* Y)
{
    float r = th * (float)(M_PI / 180.0);
    float s, c;
    __sincosf(r, &s, &c);
    float lx[4] = {-0.5f * w,  0.5f * w, 0.5f * w, -0.5f * w};
    float ly[4] = {-0.5f * h, -0.5f * h, 0.5f * h,  0.5f * h};
    #pragma unroll
    for (int k = 0; k < 4; k++) {
        X[k] = cx + lx[k] * c - ly[k] * s;
        Y[k] = cy + lx[k] * s + ly[k] * c;
    }
}

// ---------------- kernel 1: assign + (last block per image) force match ---
__global__ void assign_kernel(const float* __restrict__ anchors,
                              const float* __restrict__ gt_boxes,
                              const int*   __restrict__ gt_labels,
                              int N, int G)
{
    int b  = blockIdx.y;
    int i0 = blockIdx.x * ABLK;
    int t  = threadIdx.x;
    int i  = i0 + t;

    __shared__ float sgx[MAXG][4], sgy[MAXG][4];
    __shared__ float sgb[MAXG][5];
    __shared__ float sg_sz[MAXG];
    __shared__ float sg_area[MAXG];
    __shared__ int   s_gl[MAXG];
    __shared__ unsigned long long s_best[MAXG];
    __shared__ float s_anc[ABLK][5];
    __shared__ float s_acx[ABLK][4], s_acy[ABLK][4];
    __shared__ float s_iou[ABLK][MAXG];
    __shared__ int   s_q[ABLK * MAXG];
    __shared__ int   s_qn;
    __shared__ int   s_last;

    if (t == 0) { s_qn = 0; s_last = 0; }
    if (t < G) {
        const float* gb = gt_boxes + (size_t)(b * G + t) * 5;
        float w = gb[2], h = gb[3];
        #pragma unroll
        for (int k = 0; k < 5; k++) sgb[t][k] = gb[k];
        sg_sz[t]   = fmaxf(w, h);
        sg_area[t] = w * h;
        s_gl[t]    = gt_labels[b * G + t];
        make_corners_f(gb[0], gb[1], w, h, gb[4], sgx[t], sgy[t]);
        s_best[t] = 0ULL;
    }
    if (i < N) {
        const float* ab = anchors + (size_t)i * 5;
        #pragma unroll
        for (int k = 0; k < 5; k++) s_anc[t][k] = ab[k];
        make_corners_f(ab[0], ab[1], ab[2], ab[3], ab[4], s_acx[t], s_acy[t]);
    }
    for (int j = 0; j < G; j++) s_iou[t][j] = 0.0f;
    __syncthreads();

    // phase 1: gate, build pair queue
    if (i < N) {
        float ax = s_anc[t][0], ay = s_anc[t][1];
        float a_sz = fmaxf(s_anc[t][2], s_anc[t][3]);
        for (int j = 0; j < G; j++) {
            float dx = ax - sgb[j][0];
            float dy = ay - sgb[j][1];
            float gate = (a_sz + sg_sz[j]) * 0.7f;
            if (sqrtf(dx * dx + dy * dy) < gate) {
                int p = atomicAdd(&s_qn, 1);
                s_q[p] = (t << 5) | j;
            }
        }
    }
    __syncthreads();

    // phase 2: all threads drain the queue (load-balanced)
    int qn = s_qn;
    for (int q = t; q < qn; q += ABLK) {
        int e  = s_q[q];
        int li = e >> 5;
        int j  = e & 31;
        float a_area = s_anc[li][2] * s_anc[li][3];
        float inter = quad_clip_area(s_acx[li], s_acy[li], sgx[j], sgy[j]);
        s_iou[li][j] = inter / (a_area + sg_area[j] - inter + 1e-8f);
    }
    __syncthreads();

    // phase 3: per-anchor argmax, thresholds, per-GT best via packed atomicMax
    if (i < N) {
        float best_iou = 0.0f;
        int   best_j   = 0;
        for (int j = 0; j < G; j++) {
            float iou = s_iou[t][j];
            if (iou > best_iou) { best_iou = iou; best_j = j; }
            if (iou > 0.0f) {
                unsigned long long key =
                    ((unsigned long long)__float_as_uint(iou) << 32)
                    | (unsigned long long)(0xFFFFFFFFu - (unsigned)i);
                atomicMax(&s_best[j], key);
            }
        }
        int lab;
        if (best_iou >= 0.5f) {
            lab = s_gl[best_j] + 1;
            #pragma unroll
            for (int k = 0; k < 5; k++)
                g_mg[(size_t)(b * MAXN + i) * 5 + k] = sgb[best_j][k];
        } else {
            lab = (best_iou < 0.4f) ? 0 : -1;
        }
        g_lab[b * MAXN + i] = lab;
    }
    __syncthreads();

    if (t < G && s_best[t] != 0ULL)
        atomicMax(&g_best[b * MAXG + t], s_best[t]);

    __syncthreads();
    if (t == 0) {
        __threadfence();
        int v = atomicAdd(&g_cnt1[b], 1);
        if (v == (int)gridDim.x - 1) s_last = 1;
    }
    __syncthreads();
    if (s_last && t == 0) {
        __threadfence();
        for (int j = 0; j < G; j++) {
            unsigned long long key = g_best[b * MAXG + j];
            g_best[b * MAXG + j] = 0ULL;
            if ((key >> 32) != 0ULL) {
                int bi = (int)(0xFFFFFFFFu - (unsigned)(key & 0xFFFFFFFFu));
                int gl = s_gl[j] + 1;
                if (g_lab[b * MAXN + bi] != gl) {
                    g_lab[b * MAXN + bi] = gl;
                    #pragma unroll
                    for (int k = 0; k < 5; k++)
                        g_mg[(size_t)(b * MAXN + bi) * 5 + k] = sgb[j][k];
                }
            }
        }
        g_cnt1[b] = 0;
    }
}

// ---------------- kernel 2: loss, element-parallel float4 -----------------
__device__ __forceinline__ float focal_term(float x, bool tt) {
    float e     = __expf(-x);
    float denom = 1.0f + e;
    float L     = __logf(denom);
    float inv   = __fdividef(1.0f, denom);  // sigmoid(x)
    float om    = tt ? e * inv : inv;       // 1 - p_t
    float alpha = tt ? 0.25f : 0.75f;
    float bce   = tt ? L : (L + x);
    return alpha * om * om * bce;
}

__global__ void loss_kernel(const float* __restrict__ logits,
                            const float* __restrict__ box_reg,
                            const float* __restrict__ anchors,
                            float* __restrict__ out,
                            int N, int C, int B)
{
    int b = blockIdx.y;
    int t = threadIdx.x;
    int gtid   = blockIdx.x * LBLK + t;
    int stride = gridDim.x * LBLK;

    float fl_acc = 0.0f, rl_acc = 0.0f, np_acc = 0.0f;

    // ---- focal: flat element space, float4 vector loads ----
    int E  = N * C;           // divisible by 4 when N is (C*4 | E)
    int E4 = E >> 2;
    const float4* lp4 = (const float4*)(logits + (size_t)b * E);
    const int* labp = &g_lab[b * MAXN];

    for (int q = gtid; q < E4; q += stride) {
        float4 v = lp4[q];
        int e0 = q << 2;
        #pragma unroll
        for (int u = 0; u < 4; u++) {
            int e = e0 + u;
            int i = e / C;
            int c = e - i * C;
            int lab = labp[i];
            if (lab >= 0) {
                bool tt = (lab > 0) && (c == lab - 1);
                float x = (u == 0) ? v.x : (u == 1) ? v.y : (u == 2) ? v.z : v.w;
                fl_acc += focal_term(x, tt);
            }
        }
    }
    // scalar tail (E not multiple of 4)
    for (int e = (E4 << 2) + gtid; e < E; e += stride) {
        int i = e / C;
        int c = e - i * C;
        int lab = labp[i];
        if (lab >= 0) {
            bool tt = (lab > 0) && (c == lab - 1);
            fl_acc += focal_term(logits[(size_t)b * E + e], tt);
        }
    }

    // ---- reg loss + npos over anchors ----
    for (int i = gtid; i < N; i += stride) {
        int lab = labp[i];
        if (lab > 0) {
            np_acc += 1.0f;
            const float* ab = anchors + (size_t)i * 5;
            const float* mg = &g_mg[(size_t)(b * MAXN + i) * 5];
            const float* br = box_reg + ((size_t)b * N + i) * 5;
            float dlt[5];
            dlt[0] = (mg[0] - ab[0]) / ab[2];
            dlt[1] = (mg[1] - ab[1]) / ab[3];
            dlt[2] = logf(mg[2] / ab[2]);
            dlt[3] = logf(mg[3] / ab[3]);
            dlt[4] = jrem180(mg[4] - ab[4] + 90.0f) - 90.0f;
            float l = 0.0f;
            #pragma unroll
            for (int k = 0; k < 4; k++) {
                float d = fabsf(br[k] - dlt[k]);
                l += (d < 1.0f) ? 0.5f * d * d : d - 0.5f;
            }
            float da = fabsf(jrem180(br[4] - dlt[4] + 90.0f) - 90.0f);
            l += (da < 1.0f) ? 0.5f * da * da : da - 0.5f;
            rl_acc += l;
        }
    }

    // ---- block reduction ----
    __shared__ float sf[LBLK], sr[LBLK], sn[LBLK];
    __shared__ int   s_last;
    if (t == 0) s_last = 0;
    sf[t] = fl_acc; sr[t] = rl_acc; sn[t] = np_acc;
    __syncthreads();
    for (int s = LBLK / 2; s > 0; s >>= 1) {
        if (t < s) { sf[t] += sf[t + s]; sr[t] += sr[t + s]; sn[t] += sn[t + s]; }
        __syncthreads();
    }
    if (t == 0) {
        size_t o = (size_t)(b * MAXPB + blockIdx.x) * 3;
        g_part[o + 0] = (double)sf[0];
        g_part[o + 1] = (double)sr[0];
        g_part[o + 2] = (double)sn[0];
        __threadfence();
        int total = (int)(gridDim.x * gridDim.y);
        int v = atomicAdd(&g_cnt2, 1);
        if (v == total - 1) s_last = 1;
    }
    __syncthreads();

    // ---- last block: final reduction ----
    if (s_last) {
        if (t == 0) __threadfence();
        __syncthreads();
        __shared__ double df[LBLK], dr[LBLK], dn[LBLK];
        int nblk = (int)gridDim.x;
        double cls_m = 0.0, reg_m = 0.0;
        for (int bb = 0; bb < B; bb++) {
            double f = 0.0, r = 0.0, n = 0.0;
            for (int k = t; k < nblk; k += LBLK) {
                size_t o = (size_t)(bb * MAXPB + k) * 3;
                f += g_part[o + 0];
                r += g_part[o + 1];
                n += g_part[o + 2];
            }
            df[t] = f; dr[t] = r; dn[t] = n;
            __syncthreads();
            for (int s = LBLK / 2; s > 0; s >>= 1) {
                if (t < s) { df[t] += df[t+s]; dr[t] += dr[t+s]; dn[t] += dn[t+s]; }
                __syncthreads();
            }
            if (t == 0) {
                double npos = (dn[0] < 1.0) ? 1.0 : dn[0];
                cls_m += df[0] / npos;
                reg_m += dr[0] / npos;
            }
            __syncthreads();
        }
        if (t == 0) {
            cls_m /= (double)B;
            reg_m /= (double)B;
            out[0] = (float)(cls_m + reg_m);
            out[1] = (float)cls_m;
            out[2] = (float)reg_m;
            g_cnt2 = 0;
        }
    }
}

// ---------------- launch ----------------
extern "C" void kernel_launch(void* const* d_in, const int* in_sizes, int n_in,
                              void* d_out, int out_size)
{
    const float* logits  = (const float*)d_in[0];
    const float* breg    = (const float*)d_in[1];
    const float* anchors = (const float*)d_in[2];
    const float* gtb     = (const float*)d_in[3];
    const int*   gtl     = (const int*)d_in[4];

    int N = in_sizes[2] / 5;
    int B = in_sizes[1] / (5 * N);
    int C = in_sizes[0] / (B * N);
    int G = in_sizes[4] / B;

    dim3 ag((N + ABLK - 1) / ABLK, B);
    assign_kernel<<<ag, ABLK>>>(anchors, gtb, gtl, N, G);

    dim3 lg(LGX, B);
    loss_kernel<<<lg, LBLK>>>(logits, breg, anchors, (float*)d_out, N, C, B);
}